// round 5
// baseline (speedup 1.0000x reference)
#include <cuda_runtime.h>
#include <cuda_fp16.h>

// GCN: 2x GCNConv (sym-norm, self-loops) + ReLU + final linear.
// N=100000, E=3.2M, dims 128->32->16->1.
// CSR-by-dst per replay; norm factored (features pre-scaled by dinv);
// gathered feature tables stored fp16 (fp32 accumulate) to halve L2 traffic.

#define NMAX 100000
#define EMAX 3200000
#define SCAN_T 1024

__device__ int g_is64;
__device__ __align__(16) int    g_csr [EMAX];
__device__ __align__(16) int    g_cnt [NMAX];
__device__ __align__(16) int    g_rowp[NMAX];
__device__ __align__(16) int    g_wcur[NMAX];
__device__ __align__(16) float  g_dinv[NMAX];
__device__ __align__(16) __half g_h1  [NMAX * 32];  // dinv-prescaled x@W1 (fp16)
__device__ __align__(16) float  g_a1  [NMAX * 32];  // relu(agg1 + b1)
__device__ __align__(16) __half g_h2  [NMAX * 16];  // dinv-prescaled a1@W2 (fp16)

// ------------------------------------------- zero counts + dtype detection
// int32 data read as int64 has a uniform [0,1e5) value in the high word ->
// 16 consecutive in-range int64 reads is conclusive for genuine int64.
__global__ void k_init(const void* ei, int N) {
    int i = blockIdx.x * blockDim.x + threadIdx.x;
    if (i < N) g_cnt[i] = 0;
    if (i == 0) {
        const long long* p = (const long long*)ei;
        int ok = 1;
        for (int k = 0; k < 16; k++) {
            long long v = p[k];
            if (v < 0 || v >= N) ok = 0;
        }
        g_is64 = ok;
    }
}

// ----------------------------------------------------- dst-degree counting
__global__ void k_count(const void* ei, int E) {
    int e = blockIdx.x * blockDim.x + threadIdx.x;
    if (e >= E) return;
    int d = g_is64 ? (int)((const long long*)ei)[(long long)E + e]
                   : ((const int*)ei)[E + e];
    atomicAdd(&g_cnt[d], 1);
}

// ------------------------- single-block exclusive scan -> rowp, wcur
__global__ __launch_bounds__(SCAN_T) void k_scan(int N) {
    __shared__ int wsum[SCAN_T / 32];
    int t = threadIdx.x, lane = t & 31, w = t >> 5;
    int C = (N + SCAN_T - 1) / SCAN_T;
    int beg = t * C;
    int end = beg + C < N ? beg + C : N;
    int sum = 0;
    for (int j = beg; j < end; j++) sum += g_cnt[j];

    int acc = sum;
#pragma unroll
    for (int off = 1; off < 32; off <<= 1) {
        int add = __shfl_up_sync(0xffffffffu, acc, off);
        if (lane >= off) acc += add;
    }
    if (lane == 31) wsum[w] = acc;
    __syncthreads();
    if (w == 0) {
        int ws = (lane < SCAN_T / 32) ? wsum[lane] : 0;
        int wa = ws;
#pragma unroll
        for (int off = 1; off < SCAN_T / 32; off <<= 1) {
            int add = __shfl_up_sync(0xffffffffu, wa, off);
            if (lane >= off) wa += add;
        }
        if (lane < SCAN_T / 32) wsum[lane] = wa - ws;   // exclusive warp offsets
    }
    __syncthreads();
    int run = (acc - sum) + wsum[w];                     // exclusive prefix of chunk
    for (int j = beg; j < end; j++) {
        int cv = g_cnt[j];
        g_rowp[j] = run;
        g_wcur[j] = run;
        run += cv;
    }
}

// --------------------------------------------------------- CSR edge scatter
__global__ void k_scatter(const void* ei, int E) {
    int e = blockIdx.x * blockDim.x + threadIdx.x;
    if (e >= E) return;
    int s, d;
    if (g_is64) {
        const long long* p = (const long long*)ei;
        s = (int)p[e];
        d = (int)p[(long long)E + e];
    } else {
        const int* p = (const int*)ei;
        s = p[e];
        d = p[E + e];
    }
    int pos = atomicAdd(&g_wcur[d], 1);
    g_csr[pos] = s;
}

// ------------------- GEMM1: h1 = fp16(dinv * (x @ W1)); also write dinv
__global__ __launch_bounds__(256) void k_gemm1(const float* __restrict__ x,
                                               const float* __restrict__ W1,
                                               int N) {
    __shared__ float Ws[128 * 32];
    __shared__ float xs[32 * 129];
    int t = threadIdx.x;
    for (int i = t; i < 128 * 32; i += 256) Ws[i] = W1[i];
    int base = blockIdx.x * 32;
    for (int i = t; i < 32 * 128; i += 256) {
        int n = i >> 7, k = i & 127;
        int node = base + n;
        xs[n * 129 + k] = (node < N) ? x[(long long)node * 128 + k] : 0.0f;
    }
    __syncthreads();

    int f4 = t & 7;      // 8 groups of 4 features
    int n  = t >> 3;
    int node = base + n;

    float4 acc = make_float4(0.f, 0.f, 0.f, 0.f);
    const float4* Ws4 = (const float4*)Ws;
#pragma unroll 8
    for (int k = 0; k < 128; k++) {
        float  xv = xs[n * 129 + k];
        float4 w  = Ws4[k * 8 + f4];
        acc.x += xv * w.x; acc.y += xv * w.y;
        acc.z += xv * w.z; acc.w += xv * w.w;
    }
    if (node < N) {
        float dv = rsqrtf((float)(g_cnt[node] + 1));   // +1 self-loop
        if (f4 == 0) g_dinv[node] = dv;
        __half2 h0 = __floats2half2_rn(acc.x * dv, acc.y * dv);
        __half2 h1 = __floats2half2_rn(acc.z * dv, acc.w * dv);
        uint2 st;
        st.x = *(unsigned*)&h0;
        st.y = *(unsigned*)&h1;
        ((uint2*)g_h1)[(long long)node * 8 + f4] = st;
    }
}

// ----------- agg layer1: a1 = relu(dinv*(h1[self]+sum h1[nbr]) + b1)
// 4 threads/node, 8 fp16 features (16B) each; fp32 accumulation; unroll x4.
__global__ __launch_bounds__(256) void k_agg1(const float* __restrict__ b1, int N) {
    int idx = blockIdx.x * blockDim.x + threadIdx.x;
    int n = idx >> 2, c = idx & 3;
    if (n >= N) return;
    int beg = g_rowp[n];
    int end = beg + g_cnt[n];
    const uint4* h1 = (const uint4*)g_h1;   // 16B = 8 halves per node-chunk

    float a0 = 0, a1v = 0, a2 = 0, a3 = 0, a4 = 0, a5 = 0, a6 = 0, a7 = 0;
#define ACC8(u) do { \
        const __half2* hp = (const __half2*)&(u); \
        float2 f0 = __half22float2(hp[0]); \
        float2 f1 = __half22float2(hp[1]); \
        float2 f2 = __half22float2(hp[2]); \
        float2 f3 = __half22float2(hp[3]); \
        a0 += f0.x; a1v += f0.y; a2 += f1.x; a3 += f1.y; \
        a4 += f2.x; a5 += f2.y; a6 += f3.x; a7 += f3.y; } while (0)

    uint4 us = h1[(long long)n * 4 + c];    // self term
    ACC8(us);
    int j = beg;
    for (; j + 4 <= end; j += 4) {
        int s0 = g_csr[j], s1 = g_csr[j + 1], s2 = g_csr[j + 2], s3 = g_csr[j + 3];
        uint4 u0 = h1[(long long)s0 * 4 + c];
        uint4 u1 = h1[(long long)s1 * 4 + c];
        uint4 u2 = h1[(long long)s2 * 4 + c];
        uint4 u3 = h1[(long long)s3 * 4 + c];
        ACC8(u0); ACC8(u1); ACC8(u2); ACC8(u3);
    }
    for (; j < end; j++) {
        uint4 u = h1[(long long)g_csr[j] * 4 + c];
        ACC8(u);
    }
#undef ACC8
    float dv = g_dinv[n];
    float4 bb0 = ((const float4*)b1)[c * 2];
    float4 bb1 = ((const float4*)b1)[c * 2 + 1];
    float4 r0, r1;
    r0.x = fmaxf(a0  * dv + bb0.x, 0.f);
    r0.y = fmaxf(a1v * dv + bb0.y, 0.f);
    r0.z = fmaxf(a2  * dv + bb0.z, 0.f);
    r0.w = fmaxf(a3  * dv + bb0.w, 0.f);
    r1.x = fmaxf(a4  * dv + bb1.x, 0.f);
    r1.y = fmaxf(a5  * dv + bb1.y, 0.f);
    r1.z = fmaxf(a6  * dv + bb1.z, 0.f);
    r1.w = fmaxf(a7  * dv + bb1.w, 0.f);
    ((float4*)g_a1)[(long long)n * 8 + c * 2]     = r0;
    ((float4*)g_a1)[(long long)n * 8 + c * 2 + 1] = r1;
}

// --------------------------------- GEMM2: h2 = fp16(dinv * (a1 @ W2))
__global__ __launch_bounds__(256) void k_gemm2(const float* __restrict__ W2, int N) {
    __shared__ float Ws[32 * 16];
    int t = threadIdx.x;
    for (int i = t; i < 32 * 16; i += 256) Ws[i] = W2[i];
    __syncthreads();

    int f4 = t & 3;
    int n  = blockIdx.x * 64 + (t >> 2);
    if (n >= N) return;

    float4 acc = make_float4(0.f, 0.f, 0.f, 0.f);
    const float4* a1r = (const float4*)(g_a1 + (long long)n * 32);
    const float4* Ws4 = (const float4*)Ws;
#pragma unroll
    for (int k4 = 0; k4 < 8; k4++) {
        float4 av = a1r[k4];
        float4 w0 = Ws4[(k4 * 4 + 0) * 4 + f4];
        float4 w1 = Ws4[(k4 * 4 + 1) * 4 + f4];
        float4 w2 = Ws4[(k4 * 4 + 2) * 4 + f4];
        float4 w3 = Ws4[(k4 * 4 + 3) * 4 + f4];
        acc.x += av.x * w0.x + av.y * w1.x + av.z * w2.x + av.w * w3.x;
        acc.y += av.x * w0.y + av.y * w1.y + av.z * w2.y + av.w * w3.y;
        acc.z += av.x * w0.z + av.y * w1.z + av.z * w2.z + av.w * w3.z;
        acc.w += av.x * w0.w + av.y * w1.w + av.z * w2.w + av.w * w3.w;
    }
    float dv = g_dinv[n];
    __half2 h0 = __floats2half2_rn(acc.x * dv, acc.y * dv);
    __half2 h1 = __floats2half2_rn(acc.z * dv, acc.w * dv);
    uint2 st;
    st.x = *(unsigned*)&h0;
    st.y = *(unsigned*)&h1;
    ((uint2*)g_h2)[(long long)n * 4 + f4] = st;
}

// ------ agg layer2 + final: out = relu(dinv*sum + b2) @ Wf + bf
// 2 threads/node, 8 fp16 features (16B) each; shuffle-reduce the dot.
__global__ __launch_bounds__(256) void k_agg2(const float* __restrict__ b2,
                                              const float* __restrict__ Wf,
                                              const float* __restrict__ bf,
                                              float* __restrict__ out, int N) {
    int idx = blockIdx.x * blockDim.x + threadIdx.x;
    int n = idx >> 1, c = idx & 1;
    if (n >= N) return;
    int beg = g_rowp[n];
    int end = beg + g_cnt[n];
    const uint4* h2 = (const uint4*)g_h2;

    float a0 = 0, a1v = 0, a2 = 0, a3 = 0, a4 = 0, a5 = 0, a6 = 0, a7 = 0;
#define ACC8(u) do { \
        const __half2* hp = (const __half2*)&(u); \
        float2 f0 = __half22float2(hp[0]); \
        float2 f1 = __half22float2(hp[1]); \
        float2 f2 = __half22float2(hp[2]); \
        float2 f3 = __half22float2(hp[3]); \
        a0 += f0.x; a1v += f0.y; a2 += f1.x; a3 += f1.y; \
        a4 += f2.x; a5 += f2.y; a6 += f3.x; a7 += f3.y; } while (0)

    uint4 us = h2[(long long)n * 2 + c];    // self term
    ACC8(us);
    int j = beg;
    for (; j + 4 <= end; j += 4) {
        int s0 = g_csr[j], s1 = g_csr[j + 1], s2 = g_csr[j + 2], s3 = g_csr[j + 3];
        uint4 u0 = h2[(long long)s0 * 2 + c];
        uint4 u1 = h2[(long long)s1 * 2 + c];
        uint4 u2 = h2[(long long)s2 * 2 + c];
        uint4 u3 = h2[(long long)s3 * 2 + c];
        ACC8(u0); ACC8(u1); ACC8(u2); ACC8(u3);
    }
    for (; j < end; j++) {
        uint4 u = h2[(long long)g_csr[j] * 2 + c];
        ACC8(u);
    }
#undef ACC8
    float dv = g_dinv[n];
    float4 bb0 = ((const float4*)b2)[c * 2];
    float4 bb1 = ((const float4*)b2)[c * 2 + 1];
    float4 w0  = ((const float4*)Wf)[c * 2];
    float4 w1  = ((const float4*)Wf)[c * 2 + 1];
    float p = fmaxf(a0  * dv + bb0.x, 0.f) * w0.x
            + fmaxf(a1v * dv + bb0.y, 0.f) * w0.y
            + fmaxf(a2  * dv + bb0.z, 0.f) * w0.z
            + fmaxf(a3  * dv + bb0.w, 0.f) * w0.w
            + fmaxf(a4  * dv + bb1.x, 0.f) * w1.x
            + fmaxf(a5  * dv + bb1.y, 0.f) * w1.y
            + fmaxf(a6  * dv + bb1.z, 0.f) * w1.z
            + fmaxf(a7  * dv + bb1.w, 0.f) * w1.w;
    p += __shfl_xor_sync(0xffffffffu, p, 1);
    if (c == 0) out[n] = p + __ldg(&bf[0]);
}

// ---------------------------------------------------------------- launcher
extern "C" void kernel_launch(void* const* d_in, const int* in_sizes, int n_in,
                              void* d_out, int out_size) {
    const float* x  = (const float*)d_in[0];
    const void*  ei = d_in[1];
    const float* W1 = (const float*)d_in[2];
    const float* b1 = (const float*)d_in[3];
    const float* W2 = (const float*)d_in[4];
    const float* b2 = (const float*)d_in[5];
    const float* Wf = (const float*)d_in[6];
    const float* bf = (const float*)d_in[7];
    float* out = (float*)d_out;

    int N = in_sizes[0] / 128;   // 100000
    int E = in_sizes[1] / 2;     // 3200000

    k_init   <<<(N + 255) / 256, 256>>>(ei, N);
    k_count  <<<(E + 255) / 256, 256>>>(ei, E);
    k_scan   <<<1, SCAN_T>>>(N);
    k_scatter<<<(E + 255) / 256, 256>>>(ei, E);
    k_gemm1  <<<(N + 31) / 32, 256>>>(x, W1, N);
    k_agg1   <<<(N * 4 + 255) / 256, 256>>>(b1, N);
    k_gemm2  <<<(N + 63) / 64, 256>>>(W2, N);
    k_agg2   <<<(N * 2 + 255) / 256, 256>>>(b2, Wf, bf, out, N);
}